// round 1
// baseline (speedup 1.0000x reference)
#include <cuda_runtime.h>
#include <math.h>

#define DIMC 1024
#define HEADS 16
#define HEAD_DIM 64
#define BATCH 2
#define TQ 2048
#define TK 2048
#define MROWS (BATCH * TQ) /* 4096 */

// Scratch (device globals: no alloc allowed)
__device__ float g_q[(size_t)MROWS * DIMC];
__device__ float g_k[(size_t)MROWS * DIMC];
__device__ float g_v[(size_t)MROWS * DIMC];
__device__ float g_o[(size_t)MROWS * DIMC];

// ---------------------------------------------------------------------------
// Tiled fp32 NT GEMM: C[M,N] = A[M,K] @ W[N,K]^T + bias[N]
// 128x128 block tile, BK=16, 256 threads, 8x8 microtile per thread.
// ---------------------------------------------------------------------------
__device__ __forceinline__ void gemm_body(
    const float* __restrict__ A, const float* __restrict__ W,
    const float* __restrict__ bias, float* __restrict__ C,
    int M, int N, int K)
{
    __shared__ float As[16][132];
    __shared__ float Bs[16][132];

    const int tid = threadIdx.x;
    const int tx = tid & 15;   // 0..15 -> N microtile
    const int ty = tid >> 4;   // 0..15 -> M microtile
    const int bm = blockIdx.y * 128;
    const int bn = blockIdx.x * 128;

    float acc[8][8];
#pragma unroll
    for (int i = 0; i < 8; i++)
#pragma unroll
        for (int j = 0; j < 8; j++) acc[i][j] = 0.0f;

    for (int k0 = 0; k0 < K; k0 += 16) {
#pragma unroll
        for (int it = 0; it < 2; it++) {
            int f = tid + it * 256;       // 0..511
            int r = f >> 2;               // 0..127
            int kq = f & 3;               // 0..3 (float4 within the 16 k's)
            float4 va = *(const float4*)(A + (size_t)(bm + r) * K + k0 + kq * 4);
            As[kq * 4 + 0][r] = va.x;
            As[kq * 4 + 1][r] = va.y;
            As[kq * 4 + 2][r] = va.z;
            As[kq * 4 + 3][r] = va.w;
            float4 vb = *(const float4*)(W + (size_t)(bn + r) * K + k0 + kq * 4);
            Bs[kq * 4 + 0][r] = vb.x;
            Bs[kq * 4 + 1][r] = vb.y;
            Bs[kq * 4 + 2][r] = vb.z;
            Bs[kq * 4 + 3][r] = vb.w;
        }
        __syncthreads();

#pragma unroll
        for (int kk = 0; kk < 16; kk++) {
            float a[8], b[8];
            *(float4*)&a[0] = *(const float4*)&As[kk][ty * 4];
            *(float4*)&a[4] = *(const float4*)&As[kk][ty * 4 + 64];
            *(float4*)&b[0] = *(const float4*)&Bs[kk][tx * 4];
            *(float4*)&b[4] = *(const float4*)&Bs[kk][tx * 4 + 64];
#pragma unroll
            for (int i = 0; i < 8; i++)
#pragma unroll
                for (int j = 0; j < 8; j++) acc[i][j] += a[i] * b[j];
        }
        __syncthreads();
    }

    // epilogue with bias, float4 stores
#pragma unroll
    for (int ih = 0; ih < 2; ih++) {
#pragma unroll
        for (int ii = 0; ii < 4; ii++) {
            int r = bm + ih * 64 + ty * 4 + ii;
#pragma unroll
            for (int jh = 0; jh < 2; jh++) {
                int c = bn + jh * 64 + tx * 4;
                float4 bv = *(const float4*)(bias + c);
                float4 o;
                o.x = acc[ih * 4 + ii][jh * 4 + 0] + bv.x;
                o.y = acc[ih * 4 + ii][jh * 4 + 1] + bv.y;
                o.z = acc[ih * 4 + ii][jh * 4 + 2] + bv.z;
                o.w = acc[ih * 4 + ii][jh * 4 + 3] + bv.w;
                *(float4*)(C + (size_t)r * N + c) = o;
            }
        }
    }
}

__global__ __launch_bounds__(256, 2) void gemm_nt_bias(
    const float* __restrict__ A, const float* __restrict__ W,
    const float* __restrict__ bias, float* __restrict__ C,
    int M, int N, int K)
{
    gemm_body(A, W, bias, C, M, N, K);
}

// Fused QKV projection: blockIdx.z selects which projection.
__global__ __launch_bounds__(256, 2) void gemm_qkv(
    const float* __restrict__ q_in, const float* __restrict__ k_in, const float* __restrict__ v_in,
    const float* __restrict__ wq, const float* __restrict__ wk, const float* __restrict__ wv,
    const float* __restrict__ bq, const float* __restrict__ bk, const float* __restrict__ bv,
    float* __restrict__ oq, float* __restrict__ ok, float* __restrict__ ov)
{
    const int z = blockIdx.z;
    const float* A = (z == 0) ? q_in : (z == 1) ? k_in : v_in;
    const float* W = (z == 0) ? wq : (z == 1) ? wk : wv;
    const float* bias = (z == 0) ? bq : (z == 1) ? bk : bv;
    float* C = (z == 0) ? oq : (z == 1) ? ok : ov;
    gemm_body(A, W, bias, C, MROWS, DIMC, DIMC);
}

// ---------------------------------------------------------------------------
// Flash attention (fp32, online softmax).
// Block: 256 threads, handles 64 q rows of one (b, h). 16x16 thread grid,
// each thread owns a 4x4 microtile (rows = ty*4.., cols/dims = tx*4..).
// Row state (m, l) lives in registers (replicated across the 16 tx lanes).
// ---------------------------------------------------------------------------
#define APAD 68
#define ATTN_SMEM (4 * 64 * APAD * 4)

__global__ __launch_bounds__(256, 2) void attn_kernel(
    const float* __restrict__ Q, const float* __restrict__ Kt,
    const float* __restrict__ V, const int* __restrict__ mask,
    float* __restrict__ Op)
{
    extern __shared__ float sm[];
    float(*Qs)[APAD] = (float(*)[APAD])(sm);
    float(*Ks)[APAD] = (float(*)[APAD])(sm + 64 * APAD);
    float(*Vs)[APAD] = (float(*)[APAD])(sm + 2 * 64 * APAD);
    float(*Ps)[APAD] = (float(*)[APAD])(sm + 3 * 64 * APAD);

    const int tid = threadIdx.x;
    const int tx = tid & 15;
    const int ty = tid >> 4;
    const int q0 = blockIdx.x * 64;
    const int h = blockIdx.y;
    const int b = blockIdx.z;

    const size_t baseQ = ((size_t)b * TQ + q0) * DIMC + h * HEAD_DIM;
    const size_t baseKV = (size_t)b * TK * DIMC + h * HEAD_DIM;
    const size_t maskBase = ((size_t)b * TQ + q0) * TK;

    // Load Q tile (64 rows x 64 dims)
#pragma unroll
    for (int it = 0; it < 4; it++) {
        int f = tid + it * 256;
        int r = f >> 4, c4 = f & 15;
        *(float4*)&Qs[r][c4 * 4] =
            *(const float4*)(Q + baseQ + (size_t)r * DIMC + c4 * 4);
    }

    float m[4], l[4], oacc[4][4];
#pragma unroll
    for (int i = 0; i < 4; i++) {
        m[i] = -1e30f;
        l[i] = 0.0f;
#pragma unroll
        for (int j = 0; j < 4; j++) oacc[i][j] = 0.0f;
    }

    const float scale = 0.125f; // 1/sqrt(64)

    for (int k0 = 0; k0 < TK; k0 += 64) {
        __syncthreads(); // prev PV done (and Q tile visible on first iter)
#pragma unroll
        for (int it = 0; it < 4; it++) {
            int f = tid + it * 256;
            int r = f >> 4, c4 = f & 15;
            *(float4*)&Ks[r][c4 * 4] =
                *(const float4*)(Kt + baseKV + (size_t)(k0 + r) * DIMC + c4 * 4);
            *(float4*)&Vs[r][c4 * 4] =
                *(const float4*)(V + baseKV + (size_t)(k0 + r) * DIMC + c4 * 4);
        }
        __syncthreads();

        // S = Q @ K^T (4x4 microtile per thread)
        float s[4][4];
#pragma unroll
        for (int i = 0; i < 4; i++)
#pragma unroll
            for (int j = 0; j < 4; j++) s[i][j] = 0.0f;

#pragma unroll
        for (int d4 = 0; d4 < 16; d4++) {
            float4 qa[4], kb4[4];
#pragma unroll
            for (int i = 0; i < 4; i++) qa[i] = *(const float4*)&Qs[ty * 4 + i][d4 * 4];
#pragma unroll
            for (int j = 0; j < 4; j++) kb4[j] = *(const float4*)&Ks[tx * 4 + j][d4 * 4];
#pragma unroll
            for (int i = 0; i < 4; i++)
#pragma unroll
                for (int j = 0; j < 4; j++)
                    s[i][j] += qa[i].x * kb4[j].x + qa[i].y * kb4[j].y +
                               qa[i].z * kb4[j].z + qa[i].w * kb4[j].w;
        }

        // scale, clip, mask
#pragma unroll
        for (int i = 0; i < 4; i++) {
            const int r = ty * 4 + i;
            const int4 mm = *(const int4*)(mask + maskBase + (size_t)r * TK + k0 + tx * 4);
            float v0 = fminf(fmaxf(s[i][0] * scale, -100.0f), 100.0f);
            float v1 = fminf(fmaxf(s[i][1] * scale, -100.0f), 100.0f);
            float v2 = fminf(fmaxf(s[i][2] * scale, -100.0f), 100.0f);
            float v3 = fminf(fmaxf(s[i][3] * scale, -100.0f), 100.0f);
            s[i][0] = (mm.x == 0) ? -1e30f : v0;
            s[i][1] = (mm.y == 0) ? -1e30f : v1;
            s[i][2] = (mm.z == 0) ? -1e30f : v2;
            s[i][3] = (mm.w == 0) ? -1e30f : v3;
        }

        // row max across the 16 tx lanes (xor shuffle stays within 16-lane group)
        float rmax[4];
#pragma unroll
        for (int i = 0; i < 4; i++)
            rmax[i] = fmaxf(fmaxf(s[i][0], s[i][1]), fmaxf(s[i][2], s[i][3]));
#pragma unroll
        for (int off = 8; off >= 1; off >>= 1)
#pragma unroll
            for (int i = 0; i < 4; i++)
                rmax[i] = fmaxf(rmax[i], __shfl_xor_sync(0xffffffffu, rmax[i], off));

        // online softmax update
#pragma unroll
        for (int i = 0; i < 4; i++) {
            float mn = fmaxf(m[i], rmax[i]);
            float alpha = __expf(m[i] - mn);
            float rsum = 0.0f;
#pragma unroll
            for (int j = 0; j < 4; j++) {
                float p = __expf(s[i][j] - mn);
                s[i][j] = p;
                rsum += p;
            }
#pragma unroll
            for (int off = 8; off >= 1; off >>= 1)
                rsum += __shfl_xor_sync(0xffffffffu, rsum, off);
            l[i] = l[i] * alpha + rsum;
            m[i] = mn;
#pragma unroll
            for (int j = 0; j < 4; j++) oacc[i][j] *= alpha;
        }

        // store P tile
#pragma unroll
        for (int i = 0; i < 4; i++) {
            *(float4*)&Ps[ty * 4 + i][tx * 4] =
                make_float4(s[i][0], s[i][1], s[i][2], s[i][3]);
        }
        __syncthreads();

        // O += P @ V
#pragma unroll
        for (int k4 = 0; k4 < 16; k4++) {
            float4 pa[4];
#pragma unroll
            for (int i = 0; i < 4; i++) pa[i] = *(const float4*)&Ps[ty * 4 + i][k4 * 4];
#pragma unroll
            for (int kk = 0; kk < 4; kk++) {
                float4 vb4 = *(const float4*)&Vs[k4 * 4 + kk][tx * 4];
#pragma unroll
                for (int i = 0; i < 4; i++) {
                    float p = (kk == 0) ? pa[i].x : (kk == 1) ? pa[i].y
                              : (kk == 2) ? pa[i].z : pa[i].w;
                    oacc[i][0] += p * vb4.x;
                    oacc[i][1] += p * vb4.y;
                    oacc[i][2] += p * vb4.z;
                    oacc[i][3] += p * vb4.w;
                }
            }
        }
    }

    // epilogue: normalize and write
#pragma unroll
    for (int i = 0; i < 4; i++) {
        float inv = 1.0f / l[i];
        int r = ty * 4 + i;
        float4 o4 = make_float4(oacc[i][0] * inv, oacc[i][1] * inv,
                                oacc[i][2] * inv, oacc[i][3] * inv);
        *(float4*)(Op + baseQ + (size_t)r * DIMC + tx * 4) = o4;
    }
}

// ---------------------------------------------------------------------------
extern "C" void kernel_launch(void* const* d_in, const int* in_sizes, int n_in,
                              void* d_out, int out_size)
{
    const float* query = (const float*)d_in[0];
    const float* key = (const float*)d_in[1];
    const float* value = (const float*)d_in[2];
    const int* mask = (const int*)d_in[3];
    const float* wq = (const float*)d_in[4];
    const float* wk = (const float*)d_in[5];
    const float* wv = (const float*)d_in[6];
    const float* wo = (const float*)d_in[7];
    const float* bq = (const float*)d_in[8];
    const float* bk = (const float*)d_in[9];
    const float* bv = (const float*)d_in[10];
    const float* bo = (const float*)d_in[11];

    float *pq, *pk, *pv, *po;
    cudaGetSymbolAddress((void**)&pq, g_q);
    cudaGetSymbolAddress((void**)&pk, g_k);
    cudaGetSymbolAddress((void**)&pv, g_v);
    cudaGetSymbolAddress((void**)&po, g_o);

    static int attn_attr_set = 0;
    if (!attn_attr_set) {
        cudaFuncSetAttribute(attn_kernel,
                             cudaFuncAttributeMaxDynamicSharedMemorySize, ATTN_SMEM);
        attn_attr_set = 1;
    }

    dim3 gqkv(DIMC / 128, MROWS / 128, 3);
    gemm_qkv<<<gqkv, 256>>>(query, key, value, wq, wk, wv, bq, bk, bv, pq, pk, pv);

    dim3 gattn(TQ / 64, HEADS, BATCH);
    attn_kernel<<<gattn, 256, ATTN_SMEM>>>(pq, pk, pv, mask, po);

    dim3 gout(DIMC / 128, MROWS / 128);
    gemm_nt_bias<<<gout, 256>>>(po, wo, bo, (float*)d_out, MROWS, DIMC, DIMC);
}

// round 3
// speedup vs baseline: 1.1082x; 1.1082x over previous
#include <cuda_runtime.h>
#include <cuda_bf16.h>
#include <cstdint>
#include <math.h>

#define DIMC 1024
#define HEADS 16
#define HEAD_DIM 64
#define BATCH 2
#define TQ 2048
#define TK 2048
#define MROWS (BATCH * TQ) /* 4096 */

// ---------------------------------------------------------------------------
// Scratch (device globals: no alloc allowed)
// ---------------------------------------------------------------------------
__device__ float g_q[(size_t)MROWS * DIMC];
__device__ float g_k[(size_t)MROWS * DIMC];
__device__ float g_v[(size_t)MROWS * DIMC];
__device__ float g_o[(size_t)MROWS * DIMC];

// bf16 hi/lo splits
__device__ __nv_bfloat16 g_qh[(size_t)MROWS * DIMC];
__device__ __nv_bfloat16 g_ql[(size_t)MROWS * DIMC];
__device__ __nv_bfloat16 g_kh[(size_t)MROWS * DIMC];
__device__ __nv_bfloat16 g_kl[(size_t)MROWS * DIMC];
__device__ __nv_bfloat16 g_vh[(size_t)MROWS * DIMC];
__device__ __nv_bfloat16 g_vl[(size_t)MROWS * DIMC];
__device__ __nv_bfloat16 g_oh[(size_t)MROWS * DIMC];
__device__ __nv_bfloat16 g_ol[(size_t)MROWS * DIMC];
__device__ __nv_bfloat16 g_wqh[(size_t)DIMC * DIMC];
__device__ __nv_bfloat16 g_wql[(size_t)DIMC * DIMC];
__device__ __nv_bfloat16 g_wkh[(size_t)DIMC * DIMC];
__device__ __nv_bfloat16 g_wkl[(size_t)DIMC * DIMC];
__device__ __nv_bfloat16 g_wvh[(size_t)DIMC * DIMC];
__device__ __nv_bfloat16 g_wvl[(size_t)DIMC * DIMC];
__device__ __nv_bfloat16 g_woh[(size_t)DIMC * DIMC];
__device__ __nv_bfloat16 g_wol[(size_t)DIMC * DIMC];

// ---------------------------------------------------------------------------
// Helpers
// ---------------------------------------------------------------------------
__device__ __forceinline__ uint32_t smem_u32(const void* p) {
    uint32_t a;
    asm("{ .reg .u64 t; cvta.to.shared.u64 t, %1; cvt.u32.u64 %0, t; }" : "=r"(a) : "l"(p));
    return a;
}
__device__ __forceinline__ void cpa16(uint32_t dst, const void* src) {
    asm volatile("cp.async.cg.shared.global [%0], [%1], 16;" :: "r"(dst), "l"(src) : "memory");
}
#define CP_COMMIT() asm volatile("cp.async.commit_group;" ::: "memory")
#define CP_WAIT(n)  asm volatile("cp.async.wait_group %0;" :: "n"(n) : "memory")

__device__ __forceinline__ void ldsm_x4(uint32_t& r0, uint32_t& r1, uint32_t& r2, uint32_t& r3,
                                        uint32_t addr) {
    asm volatile("ldmatrix.sync.aligned.m8n8.x4.shared.b16 {%0,%1,%2,%3}, [%4];"
                 : "=r"(r0), "=r"(r1), "=r"(r2), "=r"(r3) : "r"(addr));
}
__device__ __forceinline__ void mma16816(float* c, uint32_t a0, uint32_t a1, uint32_t a2,
                                         uint32_t a3, uint32_t b0, uint32_t b1) {
    asm volatile(
        "mma.sync.aligned.m16n8k16.row.col.f32.bf16.bf16.f32 "
        "{%0,%1,%2,%3}, {%4,%5,%6,%7}, {%8,%9}, {%0,%1,%2,%3};"
        : "+f"(c[0]), "+f"(c[1]), "+f"(c[2]), "+f"(c[3])
        : "r"(a0), "r"(a1), "r"(a2), "r"(a3), "r"(b0), "r"(b1));
}

// ---------------------------------------------------------------------------
// fp32 -> bf16 hi/lo split
// ---------------------------------------------------------------------------
__global__ void split_bf16(const float* __restrict__ src, __nv_bfloat16* __restrict__ hi,
                           __nv_bfloat16* __restrict__ lo, int n) {
    int i = (blockIdx.x * blockDim.x + threadIdx.x) * 4;
    if (i >= n) return;
    float4 v = *(const float4*)(src + i);
    __nv_bfloat16 h0 = __float2bfloat16(v.x);
    __nv_bfloat16 h1 = __float2bfloat16(v.y);
    __nv_bfloat16 h2 = __float2bfloat16(v.z);
    __nv_bfloat16 h3 = __float2bfloat16(v.w);
    __nv_bfloat162 hp0; hp0.x = h0; hp0.y = h1;
    __nv_bfloat162 hp1; hp1.x = h2; hp1.y = h3;
    *(__nv_bfloat162*)(hi + i) = hp0;
    *(__nv_bfloat162*)(hi + i + 2) = hp1;
    __nv_bfloat162 lp0, lp1;
    lp0.x = __float2bfloat16(v.x - __bfloat162float(h0));
    lp0.y = __float2bfloat16(v.y - __bfloat162float(h1));
    lp1.x = __float2bfloat16(v.z - __bfloat162float(h2));
    lp1.y = __float2bfloat16(v.w - __bfloat162float(h3));
    *(__nv_bfloat162*)(lo + i) = lp0;
    *(__nv_bfloat162*)(lo + i + 2) = lp1;
}

// ---------------------------------------------------------------------------
// HMMA bf16-split NT GEMM: C[M,N] = (Ah+Al)[M,K] @ (Bh+Bl)[N,K]^T + bias
// CTA 128x128, 8 warps (warp tile 32x64), BK=32, double-buffered cp.async.
// 3 K-passes: Ah*Bh, Ah*Bl, Al*Bh.
// ---------------------------------------------------------------------------
#define PITCH 40           /* bf16 elems per smem row: 80B, 16B-aligned, conflict-free */
#define PITCHB (PITCH * 2)

__device__ __forceinline__ void ld_chunk(
    uint32_t a_s, uint32_t b_s,
    const __nv_bfloat16* __restrict__ A, const __nv_bfloat16* __restrict__ B,
    int bm, int bn, int ks, int K, int tid)
{
#pragma unroll
    for (int it = 0; it < 2; it++) {
        int f = tid + it * 256;
        int r = f >> 2;   // 0..127
        int c = f & 3;    // 16B unit
        cpa16(a_s + r * PITCHB + c * 16, A + (size_t)(bm + r) * K + ks + c * 8);
        cpa16(b_s + r * PITCHB + c * 16, B + (size_t)(bn + r) * K + ks + c * 8);
    }
}

__device__ __forceinline__ void gemm_mma_body(
    const __nv_bfloat16* __restrict__ Ah, const __nv_bfloat16* __restrict__ Al,
    const __nv_bfloat16* __restrict__ Bh, const __nv_bfloat16* __restrict__ Bl,
    const float* __restrict__ bias, float* __restrict__ C,
    int M, int N, int K)
{
    __shared__ alignas(128) __nv_bfloat16 As[2][128 * PITCH];
    __shared__ alignas(128) __nv_bfloat16 Bs[2][128 * PITCH];

    const int tid = threadIdx.x;
    const int wid = tid >> 5;
    const int lane = tid & 31;
    const int wm = wid & 3;    // 4 M slots of 32 rows
    const int wn = wid >> 2;   // 2 N slots of 64 cols
    const int bm = blockIdx.y * 128;
    const int bn = blockIdx.x * 128;

    const uint32_t a_sm[2] = { smem_u32(As[0]), smem_u32(As[1]) };
    const uint32_t b_sm[2] = { smem_u32(Bs[0]), smem_u32(Bs[1]) };

    float acc[2][8][4];
#pragma unroll
    for (int mt = 0; mt < 2; mt++)
#pragma unroll
        for (int j = 0; j < 8; j++)
#pragma unroll
            for (int q = 0; q < 4; q++) acc[mt][j][q] = 0.0f;

    const int kchunks = K >> 5;          // 32
    const int nch = 3 * kchunks;         // 96
    const __nv_bfloat16* Asrc[3] = { Ah, Ah, Al };
    const __nv_bfloat16* Bsrc[3] = { Bh, Bl, Bh };

    // ldmatrix lane address components (row within 8x8 group + matrix select)
    const int lrow = (lane & 7) + (((lane >> 3) & 1) << 3); // row offset 0..15
    const int lkad = ((lane >> 4) & 1) << 3;                // k offset 0 or 8

    ld_chunk(a_sm[0], b_sm[0], Asrc[0], Bsrc[0], bm, bn, 0, K, tid);
    CP_COMMIT();

    for (int c = 0; c < nch; c++) {
        const int cb = c & 1;
        const int nb = cb ^ 1;
        if (c + 1 < nch) {
            const int cn = c + 1;
            const int pass = cn / kchunks;
            const int ks = (cn % kchunks) << 5;
            ld_chunk(a_sm[nb], b_sm[nb], Asrc[pass], Bsrc[pass], bm, bn, ks, K, tid);
            CP_COMMIT();
            CP_WAIT(1);
        } else {
            CP_WAIT(0);
        }
        __syncthreads();

#pragma unroll
        for (int ks16 = 0; ks16 < 32; ks16 += 16) {
            // A fragments: 2 m16 tiles
            uint32_t af[2][4];
#pragma unroll
            for (int mt = 0; mt < 2; mt++) {
                uint32_t addr = a_sm[cb] +
                    (uint32_t)((wm * 32 + mt * 16 + lrow) * PITCHB + (ks16 + lkad) * 2);
                ldsm_x4(af[mt][0], af[mt][1], af[mt][2], af[mt][3], addr);
            }
            // B fragments: 8 n8 tiles, loaded as 4 x4-ldmatrix (2 tiles each)
            uint32_t bf[8][2];
#pragma unroll
            for (int jp = 0; jp < 4; jp++) {
                uint32_t addr = b_sm[cb] +
                    (uint32_t)((wn * 64 + jp * 16 + lrow) * PITCHB + (ks16 + lkad) * 2);
                uint32_t r0, r1, r2, r3;
                ldsm_x4(r0, r1, r2, r3, addr);
                bf[jp * 2 + 0][0] = r0; bf[jp * 2 + 0][1] = r2;
                bf[jp * 2 + 1][0] = r1; bf[jp * 2 + 1][1] = r3;
            }
#pragma unroll
            for (int mt = 0; mt < 2; mt++)
#pragma unroll
                for (int j = 0; j < 8; j++)
                    mma16816(acc[mt][j], af[mt][0], af[mt][1], af[mt][2], af[mt][3],
                             bf[j][0], bf[j][1]);
        }
        __syncthreads();
    }

    // epilogue: bias add + store (float2 per fragment half)
    const int g = lane >> 2;
    const int t = lane & 3;
#pragma unroll
    for (int mt = 0; mt < 2; mt++) {
        const int row0 = bm + wm * 32 + mt * 16 + g;
#pragma unroll
        for (int j = 0; j < 8; j++) {
            const int col = bn + wn * 64 + j * 8 + t * 2;
            const float b0 = bias[col], b1 = bias[col + 1];
            float2 lo = make_float2(acc[mt][j][0] + b0, acc[mt][j][1] + b1);
            float2 hi = make_float2(acc[mt][j][2] + b0, acc[mt][j][3] + b1);
            *(float2*)(C + (size_t)row0 * N + col) = lo;
            *(float2*)(C + (size_t)(row0 + 8) * N + col) = hi;
        }
    }
}

__global__ __launch_bounds__(256) void gemm_mma_out(
    const __nv_bfloat16* __restrict__ Ah, const __nv_bfloat16* __restrict__ Al,
    const __nv_bfloat16* __restrict__ Bh, const __nv_bfloat16* __restrict__ Bl,
    const float* __restrict__ bias, float* __restrict__ C, int M, int N, int K)
{
    gemm_mma_body(Ah, Al, Bh, Bl, bias, C, M, N, K);
}

__global__ __launch_bounds__(256) void gemm_mma_qkv(
    const __nv_bfloat16* __restrict__ qh, const __nv_bfloat16* __restrict__ ql,
    const __nv_bfloat16* __restrict__ kh, const __nv_bfloat16* __restrict__ kl,
    const __nv_bfloat16* __restrict__ vh, const __nv_bfloat16* __restrict__ vl,
    const __nv_bfloat16* __restrict__ wqh, const __nv_bfloat16* __restrict__ wql,
    const __nv_bfloat16* __restrict__ wkh, const __nv_bfloat16* __restrict__ wkl,
    const __nv_bfloat16* __restrict__ wvh, const __nv_bfloat16* __restrict__ wvl,
    const float* __restrict__ bq, const float* __restrict__ bk, const float* __restrict__ bv,
    float* __restrict__ oq, float* __restrict__ ok, float* __restrict__ ov)
{
    const int z = blockIdx.z;
    const __nv_bfloat16* Ah = (z == 0) ? qh : (z == 1) ? kh : vh;
    const __nv_bfloat16* Al = (z == 0) ? ql : (z == 1) ? kl : vl;
    const __nv_bfloat16* Bh = (z == 0) ? wqh : (z == 1) ? wkh : wvh;
    const __nv_bfloat16* Bl = (z == 0) ? wql : (z == 1) ? wkl : wvl;
    const float* bias = (z == 0) ? bq : (z == 1) ? bk : bv;
    float* C = (z == 0) ? oq : (z == 1) ? ok : ov;
    gemm_mma_body(Ah, Al, Bh, Bl, bias, C, MROWS, DIMC, DIMC);
}

// ---------------------------------------------------------------------------
// Flash attention (fp32, online softmax) — unchanged from R1
// ---------------------------------------------------------------------------
#define APAD 68
#define ATTN_SMEM (4 * 64 * APAD * 4)

__global__ __launch_bounds__(256, 2) void attn_kernel(
    const float* __restrict__ Q, const float* __restrict__ Kt,
    const float* __restrict__ V, const int* __restrict__ mask,
    float* __restrict__ Op)
{
    extern __shared__ float sm[];
    float(*Qs)[APAD] = (float(*)[APAD])(sm);
    float(*Ks)[APAD] = (float(*)[APAD])(sm + 64 * APAD);
    float(*Vs)[APAD] = (float(*)[APAD])(sm + 2 * 64 * APAD);
    float(*Ps)[APAD] = (float(*)[APAD])(sm + 3 * 64 * APAD);

    const int tid = threadIdx.x;
    const int tx = tid & 15;
    const int ty = tid >> 4;
    const int q0 = blockIdx.x * 64;
    const int h = blockIdx.y;
    const int b = blockIdx.z;

    const size_t baseQ = ((size_t)b * TQ + q0) * DIMC + h * HEAD_DIM;
    const size_t baseKV = (size_t)b * TK * DIMC + h * HEAD_DIM;
    const size_t maskBase = ((size_t)b * TQ + q0) * TK;

#pragma unroll
    for (int it = 0; it < 4; it++) {
        int f = tid + it * 256;
        int r = f >> 4, c4 = f & 15;
        *(float4*)&Qs[r][c4 * 4] =
            *(const float4*)(Q + baseQ + (size_t)r * DIMC + c4 * 4);
    }

    float m[4], l[4], oacc[4][4];
#pragma unroll
    for (int i = 0; i < 4; i++) {
        m[i] = -1e30f;
        l[i] = 0.0f;
#pragma unroll
        for (int j = 0; j < 4; j++) oacc[i][j] = 0.0f;
    }

    const float scale = 0.125f;

    for (int k0 = 0; k0 < TK; k0 += 64) {
        __syncthreads();
#pragma unroll
        for (int it = 0; it < 4; it++) {
            int f = tid + it * 256;
            int r = f >> 4, c4 = f & 15;
            *(float4*)&Ks[r][c4 * 4] =
                *(const float4*)(Kt + baseKV + (size_t)(k0 + r) * DIMC + c4 * 4);
            *(float4*)&Vs[r][c4 * 4] =
                *(const float4*)(V + baseKV + (size_t)(k0 + r) * DIMC + c4 * 4);
        }
        __syncthreads();

        float s[4][4];
#pragma unroll
        for (int i = 0; i < 4; i++)
#pragma unroll
            for (int j = 0; j < 4; j++) s[i][j] = 0.0f;

#pragma unroll
        for (int d4 = 0; d4 < 16; d4++) {
            float4 qa[4], kb4[4];
#pragma unroll
            for (int i = 0; i < 4; i++) qa[i] = *(const float4*)&Qs[ty * 4 + i][d4 * 4];
#pragma unroll
            for (int j = 0; j < 4; j++) kb4[j] = *(const float4*)&Ks[tx * 4 + j][d4 * 4];
#pragma unroll
            for (int i = 0; i < 4; i++)
#pragma unroll
                for (int j = 0; j < 4; j++)
                    s[i][j] += qa[i].x * kb4[j].x + qa[i].y * kb4[j].y +
                               qa[i].z * kb4[j].z + qa[i].w * kb4[j].w;
        }

#pragma unroll
        for (int i = 0; i < 4; i++) {
            const int r = ty * 4 + i;
            const int4 mm = *(const int4*)(mask + maskBase + (size_t)r * TK + k0 + tx * 4);
            float v0 = fminf(fmaxf(s[i][0] * scale, -100.0f), 100.0f);
            float v1 = fminf(fmaxf(s[i][1] * scale, -100.0f), 100.0f);
            float v2 = fminf(fmaxf(s[i][2] * scale, -100.0f), 100.0f);
            float v3 = fminf(fmaxf(s[i][3] * scale, -100.0f), 100.0f);
            s[i][0] = (mm.x == 0) ? -1e30f : v0;
            s[i][1] = (mm.y == 0) ? -1e30f : v1;
            s[i][2] = (mm.z == 0) ? -1e30f : v2;
            s[i][3] = (mm.w == 0) ? -1e30f : v3;
        }

        float rmax[4];
#pragma unroll
        for (int i = 0; i < 4; i++)
            rmax[i] = fmaxf(fmaxf(s[i][0], s[i][1]), fmaxf(s[i][2], s[i][3]));
#pragma unroll
        for (int off = 8; off >= 1; off >>= 1)
#pragma unroll
            for (int i = 0; i < 4; i++)
                rmax[i] = fmaxf(rmax[i], __shfl_xor_sync(0xffffffffu, rmax[i], off));

#pragma unroll
        for (int i = 0; i < 4; i++) {
            float mn = fmaxf(m[i], rmax[i]);
            float alpha = __expf(m[i] - mn);
            float rsum = 0.0f;
#pragma unroll
            for (int j = 0; j < 4; j++) {
                float p = __expf(s[i][j] - mn);
                s[i][j] = p;
                rsum += p;
            }
#pragma unroll
            for (int off = 8; off >= 1; off >>= 1)
                rsum += __shfl_xor_sync(0xffffffffu, rsum, off);
            l[i] = l[i] * alpha + rsum;
            m[i] = mn;
#pragma unroll
            for (int j = 0; j < 4; j++) oacc[i][j] *= alpha;
        }

#pragma unroll
        for (int i = 0; i < 4; i++) {
            *(float4*)&Ps[ty * 4 + i][tx * 4] =
                make_float4(s[i][0], s[i][1], s[i][2], s[i][3]);
        }
        __syncthreads();

#pragma unroll
        for (int k4 = 0; k4 < 16; k4++) {
            float4 pa[4];
#pragma unroll
            for (int i = 0; i < 4; i++) pa[i] = *(const float4*)&Ps[ty * 4 + i][k4 * 4];
#pragma unroll
            for (int kk = 0; kk < 4; kk++) {
                float4 vb4 = *(const float4*)&Vs[k4 * 4 + kk][tx * 4];
#pragma unroll
                for (int i = 0; i < 4; i++) {
                    float p = (kk == 0) ? pa[i].x : (kk == 1) ? pa[i].y
                              : (kk == 2) ? pa[i].z : pa[i].w;
                    oacc[i][0] += p * vb4.x;
                    oacc[i][1] += p * vb4.y;
                    oacc[i][2] += p * vb4.z;
                    oacc[i][3] += p * vb4.w;
                }
            }
        }
    }

#pragma unroll
    for (int i = 0; i < 4; i++) {
        float inv = 1.0f / l[i];
        int r = ty * 4 + i;
        float4 o4 = make_float4(oacc[i][0] * inv, oacc[i][1] * inv,
                                oacc[i][2] * inv, oacc[i][3] * inv);
        *(float4*)(Op + baseQ + (size_t)r * DIMC + tx * 4) = o4;
    }
}

// ---------------------------------------------------------------------------
extern "C" void kernel_launch(void* const* d_in, const int* in_sizes, int n_in,
                              void* d_out, int out_size)
{
    const float* query = (const float*)d_in[0];
    const float* key = (const float*)d_in[1];
    const float* value = (const float*)d_in[2];
    const int* mask = (const int*)d_in[3];
    const float* wq = (const float*)d_in[4];
    const float* wk = (const float*)d_in[5];
    const float* wv = (const float*)d_in[6];
    const float* wo = (const float*)d_in[7];
    const float* bq = (const float*)d_in[8];
    const float* bk = (const float*)d_in[9];
    const float* bv = (const float*)d_in[10];
    const float* bo = (const float*)d_in[11];

    float *pq, *pk, *pv, *po;
    cudaGetSymbolAddress((void**)&pq, g_q);
    cudaGetSymbolAddress((void**)&pk, g_k);
    cudaGetSymbolAddress((void**)&pv, g_v);
    cudaGetSymbolAddress((void**)&po, g_o);

    __nv_bfloat16 *qh, *ql, *kh, *kl, *vh, *vl, *oh, *ol;
    __nv_bfloat16 *wqh, *wql, *wkh, *wkl, *wvh, *wvl, *woh, *wol;
    cudaGetSymbolAddress((void**)&qh, g_qh);  cudaGetSymbolAddress((void**)&ql, g_ql);
    cudaGetSymbolAddress((void**)&kh, g_kh);  cudaGetSymbolAddress((void**)&kl, g_kl);
    cudaGetSymbolAddress((void**)&vh, g_vh);  cudaGetSymbolAddress((void**)&vl, g_vl);
    cudaGetSymbolAddress((void**)&oh, g_oh);  cudaGetSymbolAddress((void**)&ol, g_ol);
    cudaGetSymbolAddress((void**)&wqh, g_wqh); cudaGetSymbolAddress((void**)&wql, g_wql);
    cudaGetSymbolAddress((void**)&wkh, g_wkh); cudaGetSymbolAddress((void**)&wkl, g_wkl);
    cudaGetSymbolAddress((void**)&wvh, g_wvh); cudaGetSymbolAddress((void**)&wvl, g_wvl);
    cudaGetSymbolAddress((void**)&woh, g_woh); cudaGetSymbolAddress((void**)&wol, g_wol);

    static int attr_set = 0;
    if (!attr_set) {
        cudaFuncSetAttribute(attn_kernel, cudaFuncAttributeMaxDynamicSharedMemorySize, ATTN_SMEM);
        attr_set = 1;
    }

    const int nAct = MROWS * DIMC;      // 4,194,304
    const int nW = DIMC * DIMC;         // 1,048,576
    split_bf16<<<nAct / 1024, 256>>>(query, qh, ql, nAct);
    split_bf16<<<nAct / 1024, 256>>>(key, kh, kl, nAct);
    split_bf16<<<nAct / 1024, 256>>>(value, vh, vl, nAct);
    split_bf16<<<nW / 1024, 256>>>(wq, wqh, wql, nW);
    split_bf16<<<nW / 1024, 256>>>(wk, wkh, wkl, nW);
    split_bf16<<<nW / 1024, 256>>>(wv, wvh, wvl, nW);
    split_bf16<<<nW / 1024, 256>>>(wo, woh, wol, nW);

    dim3 gqkv(DIMC / 128, MROWS / 128, 3);
    gemm_mma_qkv<<<gqkv, 256>>>(qh, ql, kh, kl, vh, vl,
                                wqh, wql, wkh, wkl, wvh, wvl,
                                bq, bk, bv, pq, pk, pv);

    dim3 gattn(TQ / 64, HEADS, BATCH);
    attn_kernel<<<gattn, 256, ATTN_SMEM>>>(pq, pk, pv, mask, po);

    split_bf16<<<nAct / 1024, 256>>>(po, oh, ol, nAct);

    dim3 gout(DIMC / 128, MROWS / 128);
    gemm_mma_out<<<gout, 256>>>(oh, ol, woh, wol, bo, (float*)d_out,
                                MROWS, DIMC, DIMC);
}

// round 4
// speedup vs baseline: 2.4848x; 2.2422x over previous
#include <cuda_runtime.h>
#include <cuda_bf16.h>
#include <cstdint>
#include <math.h>

#define DIMC 1024
#define HEADS 16
#define HEAD_DIM 64
#define BATCH 2
#define TQ 2048
#define TK 2048
#define MROWS (BATCH * TQ) /* 4096 */

typedef __nv_bfloat16 bf16;

// ---------------------------------------------------------------------------
// Scratch (device globals: no alloc allowed)
// ---------------------------------------------------------------------------
// input splits
__device__ bf16 g_qh[(size_t)MROWS * DIMC];
__device__ bf16 g_ql[(size_t)MROWS * DIMC];
__device__ bf16 g_kh[(size_t)MROWS * DIMC];
__device__ bf16 g_kl[(size_t)MROWS * DIMC];
__device__ bf16 g_vh[(size_t)MROWS * DIMC];
__device__ bf16 g_vl[(size_t)MROWS * DIMC];
// weight splits
__device__ bf16 g_wqh[(size_t)DIMC * DIMC];
__device__ bf16 g_wql[(size_t)DIMC * DIMC];
__device__ bf16 g_wkh[(size_t)DIMC * DIMC];
__device__ bf16 g_wkl[(size_t)DIMC * DIMC];
__device__ bf16 g_wvh[(size_t)DIMC * DIMC];
__device__ bf16 g_wvl[(size_t)DIMC * DIMC];
__device__ bf16 g_woh[(size_t)DIMC * DIMC];
__device__ bf16 g_wol[(size_t)DIMC * DIMC];
// projected q/k/v (bf16 hi/lo, written by QKV GEMM epilogue)
__device__ bf16 g_pqh[(size_t)MROWS * DIMC];
__device__ bf16 g_pql[(size_t)MROWS * DIMC];
__device__ bf16 g_pkh[(size_t)MROWS * DIMC];
__device__ bf16 g_pkl[(size_t)MROWS * DIMC];
__device__ bf16 g_pvh[(size_t)MROWS * DIMC];
__device__ bf16 g_pvl[(size_t)MROWS * DIMC];
// attention output (bf16 hi/lo, written by attention epilogue)
__device__ bf16 g_aoh[(size_t)MROWS * DIMC];
__device__ bf16 g_aol[(size_t)MROWS * DIMC];

// ---------------------------------------------------------------------------
// Helpers
// ---------------------------------------------------------------------------
__device__ __forceinline__ uint32_t smem_u32(const void* p) {
    uint32_t a;
    asm("{ .reg .u64 t; cvta.to.shared.u64 t, %1; cvt.u32.u64 %0, t; }" : "=r"(a) : "l"(p));
    return a;
}
__device__ __forceinline__ void cpa16(uint32_t dst, const void* src) {
    asm volatile("cp.async.cg.shared.global [%0], [%1], 16;" :: "r"(dst), "l"(src) : "memory");
}
#define CP_COMMIT() asm volatile("cp.async.commit_group;" ::: "memory")
#define CP_WAIT(n)  asm volatile("cp.async.wait_group %0;" :: "n"(n) : "memory")

__device__ __forceinline__ void ldsm_x4(uint32_t& r0, uint32_t& r1, uint32_t& r2, uint32_t& r3,
                                        uint32_t addr) {
    asm volatile("ldmatrix.sync.aligned.m8n8.x4.shared.b16 {%0,%1,%2,%3}, [%4];"
                 : "=r"(r0), "=r"(r1), "=r"(r2), "=r"(r3) : "r"(addr));
}
__device__ __forceinline__ void ldsm_x4_t(uint32_t& r0, uint32_t& r1, uint32_t& r2, uint32_t& r3,
                                          uint32_t addr) {
    asm volatile("ldmatrix.sync.aligned.m8n8.x4.trans.shared.b16 {%0,%1,%2,%3}, [%4];"
                 : "=r"(r0), "=r"(r1), "=r"(r2), "=r"(r3) : "r"(addr));
}
__device__ __forceinline__ void mma16816(float* c, uint32_t a0, uint32_t a1, uint32_t a2,
                                         uint32_t a3, uint32_t b0, uint32_t b1) {
    asm volatile(
        "mma.sync.aligned.m16n8k16.row.col.f32.bf16.bf16.f32 "
        "{%0,%1,%2,%3}, {%4,%5,%6,%7}, {%8,%9}, {%0,%1,%2,%3};"
        : "+f"(c[0]), "+f"(c[1]), "+f"(c[2]), "+f"(c[3])
        : "r"(a0), "r"(a1), "r"(a2), "r"(a3), "r"(b0), "r"(b1));
}
__device__ __forceinline__ uint32_t pack_hi(float a, float b) {
    __nv_bfloat162 h = __floats2bfloat162_rn(a, b);
    return *(uint32_t*)&h;
}
__device__ __forceinline__ uint32_t pack_lo(float a, float b) {
    float ra = a - __bfloat162float(__float2bfloat16(a));
    float rb = b - __bfloat162float(__float2bfloat16(b));
    __nv_bfloat162 h = __floats2bfloat162_rn(ra, rb);
    return *(uint32_t*)&h;
}

// ---------------------------------------------------------------------------
// fp32 -> bf16 hi/lo split
// ---------------------------------------------------------------------------
__global__ void split_bf16(const float* __restrict__ src, bf16* __restrict__ hi,
                           bf16* __restrict__ lo, int n) {
    int i = (blockIdx.x * blockDim.x + threadIdx.x) * 4;
    if (i >= n) return;
    float4 v = *(const float4*)(src + i);
    *(uint32_t*)(hi + i) = pack_hi(v.x, v.y);
    *(uint32_t*)(hi + i + 2) = pack_hi(v.z, v.w);
    *(uint32_t*)(lo + i) = pack_lo(v.x, v.y);
    *(uint32_t*)(lo + i + 2) = pack_lo(v.z, v.w);
}

// ---------------------------------------------------------------------------
// HMMA bf16-split NT GEMM: C = (Ah+Al)[M,K] @ (Bh+Bl)[N,K]^T + bias
// CTA 128x128, 8 warps (warp tile 32x64), BK=32, double-buffered cp.async.
// SPLIT epilogue: write bf16 hi/lo pair; else fp32.
// ---------------------------------------------------------------------------
#define PITCH 40
#define PITCHB (PITCH * 2)

__device__ __forceinline__ void ld_chunk(
    uint32_t a_s, uint32_t b_s,
    const bf16* __restrict__ A, const bf16* __restrict__ B,
    int bm, int bn, int ks, int K, int tid)
{
#pragma unroll
    for (int it = 0; it < 2; it++) {
        int f = tid + it * 256;
        int r = f >> 2;
        int c = f & 3;
        cpa16(a_s + r * PITCHB + c * 16, A + (size_t)(bm + r) * K + ks + c * 8);
        cpa16(b_s + r * PITCHB + c * 16, B + (size_t)(bn + r) * K + ks + c * 8);
    }
}

template <bool SPLIT>
__device__ __forceinline__ void gemm_mma_body(
    const bf16* __restrict__ Ah, const bf16* __restrict__ Al,
    const bf16* __restrict__ Bh, const bf16* __restrict__ Bl,
    const float* __restrict__ bias, float* __restrict__ Cf,
    bf16* __restrict__ Chi, bf16* __restrict__ Clo,
    int M, int N, int K)
{
    __shared__ alignas(128) bf16 As[2][128 * PITCH];
    __shared__ alignas(128) bf16 Bs[2][128 * PITCH];

    const int tid = threadIdx.x;
    const int wid = tid >> 5;
    const int lane = tid & 31;
    const int wm = wid & 3;
    const int wn = wid >> 2;
    const int bm = blockIdx.y * 128;
    const int bn = blockIdx.x * 128;

    const uint32_t a_sm[2] = { smem_u32(As[0]), smem_u32(As[1]) };
    const uint32_t b_sm[2] = { smem_u32(Bs[0]), smem_u32(Bs[1]) };

    float acc[2][8][4];
#pragma unroll
    for (int mt = 0; mt < 2; mt++)
#pragma unroll
        for (int j = 0; j < 8; j++)
#pragma unroll
            for (int q = 0; q < 4; q++) acc[mt][j][q] = 0.0f;

    const int kchunks = K >> 5;
    const int nch = 3 * kchunks;
    const bf16* Asrc[3] = { Ah, Ah, Al };
    const bf16* Bsrc[3] = { Bh, Bl, Bh };

    const int lrow = (lane & 7) + (((lane >> 3) & 1) << 3);
    const int lkad = ((lane >> 4) & 1) << 3;

    ld_chunk(a_sm[0], b_sm[0], Asrc[0], Bsrc[0], bm, bn, 0, K, tid);
    CP_COMMIT();

    for (int c = 0; c < nch; c++) {
        const int cb = c & 1;
        const int nb = cb ^ 1;
        if (c + 1 < nch) {
            const int cn = c + 1;
            const int pass = cn / kchunks;
            const int ks = (cn % kchunks) << 5;
            ld_chunk(a_sm[nb], b_sm[nb], Asrc[pass], Bsrc[pass], bm, bn, ks, K, tid);
            CP_COMMIT();
            CP_WAIT(1);
        } else {
            CP_WAIT(0);
        }
        __syncthreads();

#pragma unroll
        for (int ks16 = 0; ks16 < 32; ks16 += 16) {
            uint32_t af[2][4];
#pragma unroll
            for (int mt = 0; mt < 2; mt++) {
                uint32_t addr = a_sm[cb] +
                    (uint32_t)((wm * 32 + mt * 16 + lrow) * PITCHB + (ks16 + lkad) * 2);
                ldsm_x4(af[mt][0], af[mt][1], af[mt][2], af[mt][3], addr);
            }
            uint32_t bfr[8][2];
#pragma unroll
            for (int jp = 0; jp < 4; jp++) {
                uint32_t addr = b_sm[cb] +
                    (uint32_t)((wn * 64 + jp * 16 + lrow) * PITCHB + (ks16 + lkad) * 2);
                uint32_t r0, r1, r2, r3;
                ldsm_x4(r0, r1, r2, r3, addr);
                bfr[jp * 2 + 0][0] = r0; bfr[jp * 2 + 0][1] = r2;
                bfr[jp * 2 + 1][0] = r1; bfr[jp * 2 + 1][1] = r3;
            }
#pragma unroll
            for (int mt = 0; mt < 2; mt++)
#pragma unroll
                for (int j = 0; j < 8; j++)
                    mma16816(acc[mt][j], af[mt][0], af[mt][1], af[mt][2], af[mt][3],
                             bfr[j][0], bfr[j][1]);
        }
        __syncthreads();
    }

    const int g = lane >> 2;
    const int t = lane & 3;
#pragma unroll
    for (int mt = 0; mt < 2; mt++) {
        const int row0 = bm + wm * 32 + mt * 16 + g;
#pragma unroll
        for (int j = 0; j < 8; j++) {
            const int col = bn + wn * 64 + j * 8 + t * 2;
            const float b0 = bias[col], b1 = bias[col + 1];
            float f0 = acc[mt][j][0] + b0, f1 = acc[mt][j][1] + b1;
            float f2 = acc[mt][j][2] + b0, f3 = acc[mt][j][3] + b1;
            if (SPLIT) {
                *(uint32_t*)(Chi + (size_t)row0 * N + col) = pack_hi(f0, f1);
                *(uint32_t*)(Clo + (size_t)row0 * N + col) = pack_lo(f0, f1);
                *(uint32_t*)(Chi + (size_t)(row0 + 8) * N + col) = pack_hi(f2, f3);
                *(uint32_t*)(Clo + (size_t)(row0 + 8) * N + col) = pack_lo(f2, f3);
            } else {
                *(float2*)(Cf + (size_t)row0 * N + col) = make_float2(f0, f1);
                *(float2*)(Cf + (size_t)(row0 + 8) * N + col) = make_float2(f2, f3);
            }
        }
    }
}

__global__ __launch_bounds__(256) void gemm_mma_out(
    const bf16* __restrict__ Ah, const bf16* __restrict__ Al,
    const bf16* __restrict__ Bh, const bf16* __restrict__ Bl,
    const float* __restrict__ bias, float* __restrict__ C, int M, int N, int K)
{
    gemm_mma_body<false>(Ah, Al, Bh, Bl, bias, C, nullptr, nullptr, M, N, K);
}

__global__ __launch_bounds__(256) void gemm_mma_qkv(
    const bf16* __restrict__ qh, const bf16* __restrict__ ql,
    const bf16* __restrict__ kh, const bf16* __restrict__ kl,
    const bf16* __restrict__ vh, const bf16* __restrict__ vl,
    const bf16* __restrict__ wqh, const bf16* __restrict__ wql,
    const bf16* __restrict__ wkh, const bf16* __restrict__ wkl,
    const bf16* __restrict__ wvh, const bf16* __restrict__ wvl,
    const float* __restrict__ bq, const float* __restrict__ bk, const float* __restrict__ bv,
    bf16* __restrict__ pqh, bf16* __restrict__ pql,
    bf16* __restrict__ pkh, bf16* __restrict__ pkl,
    bf16* __restrict__ pvh, bf16* __restrict__ pvl)
{
    const int z = blockIdx.z;
    const bf16* Ah = (z == 0) ? qh : (z == 1) ? kh : vh;
    const bf16* Al = (z == 0) ? ql : (z == 1) ? kl : vl;
    const bf16* Bh = (z == 0) ? wqh : (z == 1) ? wkh : wvh;
    const bf16* Bl = (z == 0) ? wql : (z == 1) ? wkl : wvl;
    const float* bias = (z == 0) ? bq : (z == 1) ? bk : bv;
    bf16* Chi = (z == 0) ? pqh : (z == 1) ? pkh : pvh;
    bf16* Clo = (z == 0) ? pql : (z == 1) ? pkl : pvl;
    gemm_mma_body<true>(Ah, Al, Bh, Bl, bias, nullptr, Chi, Clo, MROWS, DIMC, DIMC);
}

// ---------------------------------------------------------------------------
// HMMA flash attention.
// CTA: 128 q rows x one (b,h). 8 warps; warp handles 16 rows.
// Q fragments preloaded from gmem into registers (hi+lo).
// K/V bf16 hi/lo tiles (64 keys) double-buffered in smem via cp.async.
// S = Qh*Kh + Qh*Kl + Ql*Kh ; O += Ph*Vh + Ph*Vl + Pl*Vh (fp32 accum).
// ---------------------------------------------------------------------------
#define KVP 72                                  /* smem pitch (elems) */
#define KV_STAGE_ELEMS (4 * 64 * KVP)           /* 18432 */
#define ATTN_SMEM (2 * KV_STAGE_ELEMS * 2)      /* 73728 B */

__global__ __launch_bounds__(256) void attn_mma(
    const bf16* __restrict__ Qh, const bf16* __restrict__ Ql,
    const bf16* __restrict__ Kh, const bf16* __restrict__ Kl,
    const bf16* __restrict__ Vh, const bf16* __restrict__ Vl,
    const int* __restrict__ mask, bf16* __restrict__ Oh, bf16* __restrict__ Ol)
{
    extern __shared__ bf16 kv[];
    const uint32_t kvb = smem_u32(kv);
    const int tid = threadIdx.x;
    const int wid = tid >> 5;
    const int lane = tid & 31;
    const int t = lane & 3;
    const int g = lane >> 2;
    const int q0 = blockIdx.x * 128;
    const int h = blockIdx.y;
    const int b = blockIdx.z;

    // ---- preload Q fragments (registers, reused across all k-tiles) ----
    const size_t rowg = (size_t)b * TQ + q0 + wid * 16 + g;
    const size_t rowg8 = rowg + 8;
    uint32_t aqh[4][4], aql[4][4];
#pragma unroll
    for (int c = 0; c < 4; c++) {
        const int col = h * HEAD_DIM + c * 16 + t * 2;
        aqh[c][0] = *(const uint32_t*)(Qh + rowg * DIMC + col);
        aqh[c][1] = *(const uint32_t*)(Qh + rowg8 * DIMC + col);
        aqh[c][2] = *(const uint32_t*)(Qh + rowg * DIMC + col + 8);
        aqh[c][3] = *(const uint32_t*)(Qh + rowg8 * DIMC + col + 8);
        aql[c][0] = *(const uint32_t*)(Ql + rowg * DIMC + col);
        aql[c][1] = *(const uint32_t*)(Ql + rowg8 * DIMC + col);
        aql[c][2] = *(const uint32_t*)(Ql + rowg * DIMC + col + 8);
        aql[c][3] = *(const uint32_t*)(Ql + rowg8 * DIMC + col + 8);
    }

    float m_[2] = { -1e30f, -1e30f };
    float l_[2] = { 0.0f, 0.0f };
    float acc_o[8][4];
#pragma unroll
    for (int j = 0; j < 8; j++)
#pragma unroll
        for (int q = 0; q < 4; q++) acc_o[j][q] = 0.0f;

    // KV stage loader: arrays per stage: [Kh | Kl | Vh | Vl], each 64 x KVP
    auto ld_kv = [&](int kt, int s) {
        const size_t rbase = (size_t)b * TK + kt * 64;
#pragma unroll
        for (int i = 0; i < 8; i++) {
            int f = tid + i * 256;            // 0..2047
            int arr = f >> 9;                 // 0..3
            int idx = f & 511;
            int r = idx >> 3, c8 = idx & 7;
            const bf16* src = (arr == 0) ? Kh : (arr == 1) ? Kl : (arr == 2) ? Vh : Vl;
            uint32_t dst = kvb + (uint32_t)(s * KV_STAGE_ELEMS + arr * (64 * KVP) +
                                            r * KVP + c8 * 8) * 2;
            cpa16(dst, src + (rbase + r) * DIMC + h * HEAD_DIM + c8 * 8);
        }
    };

    ld_kv(0, 0);
    CP_COMMIT();

    const int lrow = (lane & 7) + (((lane >> 3) & 1) << 3);
    const int lk8 = ((lane >> 4) & 1) << 3;
    const int trow = (lane & 7) + (((lane >> 3) & 1) << 3); // trans: +8 row for odd sel
    const int tcol = ((lane >> 4) & 1) << 3;                // trans: +8 col for sel>=2

    const size_t mrow0 = ((size_t)b * TQ + q0 + wid * 16 + g) * TK;
    const size_t mrow1 = mrow0 + 8 * TK;

    for (int kt = 0; kt < TK / 64; kt++) {
        const int cb = kt & 1;
        const int nb = cb ^ 1;
        if (kt + 1 < TK / 64) {
            ld_kv(kt + 1, nb);
            CP_COMMIT();
            CP_WAIT(1);
        } else {
            CP_WAIT(0);
        }
        __syncthreads();

        const uint32_t KHb = kvb + (uint32_t)(cb * KV_STAGE_ELEMS) * 2;
        const uint32_t KLb = KHb + (64 * KVP) * 2;
        const uint32_t VHb = KHb + (2 * 64 * KVP) * 2;
        const uint32_t VLb = KHb + (3 * 64 * KVP) * 2;

        // ---- S = Q K^T (3 passes) ----
        float acc_s[8][4];
#pragma unroll
        for (int j = 0; j < 8; j++)
#pragma unroll
            for (int q = 0; q < 4; q++) acc_s[j][q] = 0.0f;

#pragma unroll
        for (int pass = 0; pass < 3; pass++) {
            const uint32_t(*aq)[4] = (pass == 2) ? aql : aqh;
            const uint32_t Kb = (pass == 1) ? KLb : KHb;
#pragma unroll
            for (int c = 0; c < 4; c++) {
                uint32_t bfr[8][2];
#pragma unroll
                for (int jp = 0; jp < 4; jp++) {
                    uint32_t addr = Kb + (uint32_t)((jp * 16 + lrow) * KVP + c * 16 + lk8) * 2;
                    uint32_t r0, r1, r2, r3;
                    ldsm_x4(r0, r1, r2, r3, addr);
                    bfr[jp * 2 + 0][0] = r0; bfr[jp * 2 + 0][1] = r2;
                    bfr[jp * 2 + 1][0] = r1; bfr[jp * 2 + 1][1] = r3;
                }
#pragma unroll
                for (int j = 0; j < 8; j++)
                    mma16816(acc_s[j], aq[c][0], aq[c][1], aq[c][2], aq[c][3],
                             bfr[j][0], bfr[j][1]);
            }
        }

        // ---- scale/clip/mask + online softmax (per row-half) ----
        const int kc0 = kt * 64;
#pragma unroll
        for (int r01 = 0; r01 < 2; r01++) {
            const size_t mrow = ((r01 == 0) ? mrow0 : mrow1) + kc0;
            float mx = -1e30f;
#pragma unroll
            for (int j = 0; j < 8; j++) {
                int2 mm = *(const int2*)(mask + mrow + j * 8 + t * 2);
                float s0 = fminf(fmaxf(acc_s[j][r01 * 2 + 0] * 0.125f, -100.0f), 100.0f);
                float s1 = fminf(fmaxf(acc_s[j][r01 * 2 + 1] * 0.125f, -100.0f), 100.0f);
                s0 = (mm.x == 0) ? -1e30f : s0;
                s1 = (mm.y == 0) ? -1e30f : s1;
                acc_s[j][r01 * 2 + 0] = s0;
                acc_s[j][r01 * 2 + 1] = s1;
                mx = fmaxf(mx, fmaxf(s0, s1));
            }
            mx = fmaxf(mx, __shfl_xor_sync(0xffffffffu, mx, 1));
            mx = fmaxf(mx, __shfl_xor_sync(0xffffffffu, mx, 2));
            const float mnew = fmaxf(m_[r01], mx);
            const float alpha = __expf(m_[r01] - mnew);
            float rs = 0.0f;
#pragma unroll
            for (int j = 0; j < 8; j++) {
                float p0 = __expf(acc_s[j][r01 * 2 + 0] - mnew);
                float p1 = __expf(acc_s[j][r01 * 2 + 1] - mnew);
                acc_s[j][r01 * 2 + 0] = p0;
                acc_s[j][r01 * 2 + 1] = p1;
                rs += p0 + p1;
            }
            rs += __shfl_xor_sync(0xffffffffu, rs, 1);
            rs += __shfl_xor_sync(0xffffffffu, rs, 2);
            l_[r01] = l_[r01] * alpha + rs;
            m_[r01] = mnew;
#pragma unroll
            for (int j = 0; j < 8; j++) {
                acc_o[j][r01 * 2 + 0] *= alpha;
                acc_o[j][r01 * 2 + 1] *= alpha;
            }
        }

        // ---- O += P V (3 passes, P fragments from registers) ----
#pragma unroll
        for (int c = 0; c < 4; c++) {
            uint32_t ph[4], pl[4];
            ph[0] = pack_hi(acc_s[2 * c][0], acc_s[2 * c][1]);
            ph[1] = pack_hi(acc_s[2 * c][2], acc_s[2 * c][3]);
            ph[2] = pack_hi(acc_s[2 * c + 1][0], acc_s[2 * c + 1][1]);
            ph[3] = pack_hi(acc_s[2 * c + 1][2], acc_s[2 * c + 1][3]);
            pl[0] = pack_lo(acc_s[2 * c][0], acc_s[2 * c][1]);
            pl[1] = pack_lo(acc_s[2 * c][2], acc_s[2 * c][3]);
            pl[2] = pack_lo(acc_s[2 * c + 1][0], acc_s[2 * c + 1][1]);
            pl[3] = pack_lo(acc_s[2 * c + 1][2], acc_s[2 * c + 1][3]);
#pragma unroll
            for (int u = 0; u < 4; u++) {
                const uint32_t off = (uint32_t)((c * 16 + trow) * KVP + u * 16 + tcol) * 2;
                uint32_t vh0, vh1, vh2, vh3, vl0, vl1, vl2, vl3;
                ldsm_x4_t(vh0, vh1, vh2, vh3, VHb + off);
                ldsm_x4_t(vl0, vl1, vl2, vl3, VLb + off);
                mma16816(acc_o[2 * u + 0], ph[0], ph[1], ph[2], ph[3], vh0, vh1);
                mma16816(acc_o[2 * u + 1], ph[0], ph[1], ph[2], ph[3], vh2, vh3);
                mma16816(acc_o[2 * u + 0], ph[0], ph[1], ph[2], ph[3], vl0, vl1);
                mma16816(acc_o[2 * u + 1], ph[0], ph[1], ph[2], ph[3], vl2, vl3);
                mma16816(acc_o[2 * u + 0], pl[0], pl[1], pl[2], pl[3], vh0, vh1);
                mma16816(acc_o[2 * u + 1], pl[0], pl[1], pl[2], pl[3], vh2, vh3);
            }
        }
        __syncthreads();
    }

    // ---- epilogue: normalize, split to bf16 hi/lo, store ----
    const float inv0 = 1.0f / l_[0];
    const float inv1 = 1.0f / l_[1];
#pragma unroll
    for (int j = 0; j < 8; j++) {
        const int col = h * HEAD_DIM + j * 8 + t * 2;
        float f0 = acc_o[j][0] * inv0, f1 = acc_o[j][1] * inv0;
        float f2 = acc_o[j][2] * inv1, f3 = acc_o[j][3] * inv1;
        *(uint32_t*)(Oh + rowg * DIMC + col) = pack_hi(f0, f1);
        *(uint32_t*)(Ol + rowg * DIMC + col) = pack_lo(f0, f1);
        *(uint32_t*)(Oh + rowg8 * DIMC + col) = pack_hi(f2, f3);
        *(uint32_t*)(Ol + rowg8 * DIMC + col) = pack_lo(f2, f3);
    }
}

// ---------------------------------------------------------------------------
extern "C" void kernel_launch(void* const* d_in, const int* in_sizes, int n_in,
                              void* d_out, int out_size)
{
    const float* query = (const float*)d_in[0];
    const float* key = (const float*)d_in[1];
    const float* value = (const float*)d_in[2];
    const int* mask = (const int*)d_in[3];
    const float* wq = (const float*)d_in[4];
    const float* wk = (const float*)d_in[5];
    const float* wv = (const float*)d_in[6];
    const float* wo = (const float*)d_in[7];
    const float* bq = (const float*)d_in[8];
    const float* bk = (const float*)d_in[9];
    const float* bv = (const float*)d_in[10];
    const float* bo = (const float*)d_in[11];

    bf16 *qh, *ql, *kh, *kl, *vh, *vl;
    bf16 *wqh, *wql, *wkh, *wkl, *wvh, *wvl, *woh, *wol;
    bf16 *pqh, *pql, *pkh, *pkl, *pvh, *pvl, *aoh, *aol;
    cudaGetSymbolAddress((void**)&qh, g_qh);   cudaGetSymbolAddress((void**)&ql, g_ql);
    cudaGetSymbolAddress((void**)&kh, g_kh);   cudaGetSymbolAddress((void**)&kl, g_kl);
    cudaGetSymbolAddress((void**)&vh, g_vh);   cudaGetSymbolAddress((void**)&vl, g_vl);
    cudaGetSymbolAddress((void**)&wqh, g_wqh); cudaGetSymbolAddress((void**)&wql, g_wql);
    cudaGetSymbolAddress((void**)&wkh, g_wkh); cudaGetSymbolAddress((void**)&wkl, g_wkl);
    cudaGetSymbolAddress((void**)&wvh, g_wvh); cudaGetSymbolAddress((void**)&wvl, g_wvl);
    cudaGetSymbolAddress((void**)&woh, g_woh); cudaGetSymbolAddress((void**)&wol, g_wol);
    cudaGetSymbolAddress((void**)&pqh, g_pqh); cudaGetSymbolAddress((void**)&pql, g_pql);
    cudaGetSymbolAddress((void**)&pkh, g_pkh); cudaGetSymbolAddress((void**)&pkl, g_pkl);
    cudaGetSymbolAddress((void**)&pvh, g_pvh); cudaGetSymbolAddress((void**)&pvl, g_pvl);
    cudaGetSymbolAddress((void**)&aoh, g_aoh); cudaGetSymbolAddress((void**)&aol, g_aol);

    static int attr_set = 0;
    if (!attr_set) {
        cudaFuncSetAttribute(attn_mma, cudaFuncAttributeMaxDynamicSharedMemorySize, ATTN_SMEM);
        attr_set = 1;
    }

    const int nAct = MROWS * DIMC;
    const int nW = DIMC * DIMC;
    split_bf16<<<nAct / 1024, 256>>>(query, qh, ql, nAct);
    split_bf16<<<nAct / 1024, 256>>>(key, kh, kl, nAct);
    split_bf16<<<nAct / 1024, 256>>>(value, vh, vl, nAct);
    split_bf16<<<nW / 1024, 256>>>(wq, wqh, wql, nW);
    split_bf16<<<nW / 1024, 256>>>(wk, wkh, wkl, nW);
    split_bf16<<<nW / 1024, 256>>>(wv, wvh, wvl, nW);
    split_bf16<<<nW / 1024, 256>>>(wo, woh, wol, nW);

    dim3 gqkv(DIMC / 128, MROWS / 128, 3);
    gemm_mma_qkv<<<gqkv, 256>>>(qh, ql, kh, kl, vh, vl,
                                wqh, wql, wkh, wkl, wvh, wvl,
                                bq, bk, bv,
                                pqh, pql, pkh, pkl, pvh, pvl);

    dim3 gattn(TQ / 128, HEADS, BATCH);
    attn_mma<<<gattn, 256, ATTN_SMEM>>>(pqh, pql, pkh, pkl, pvh, pvl, mask, aoh, aol);

    dim3 gout(DIMC / 128, MROWS / 128);
    gemm_mma_out<<<gout, 256>>>(aoh, aol, woh, wol, bo, (float*)d_out,
                                MROWS, DIMC, DIMC);
}

// round 5
// speedup vs baseline: 2.8175x; 1.1339x over previous
#include <cuda_runtime.h>
#include <cuda_bf16.h>
#include <cstdint>
#include <math.h>

#define DIMC 1024
#define HEADS 16
#define HEAD_DIM 64
#define BATCH 2
#define TQ 2048
#define TK 2048
#define MROWS (BATCH * TQ) /* 4096 */

typedef __nv_bfloat16 bf16;

// ---------------------------------------------------------------------------
// Scratch (device globals: no alloc allowed)
// ---------------------------------------------------------------------------
__device__ bf16 g_qh[(size_t)MROWS * DIMC];
__device__ bf16 g_ql[(size_t)MROWS * DIMC];
__device__ bf16 g_kh[(size_t)MROWS * DIMC];
__device__ bf16 g_kl[(size_t)MROWS * DIMC];
__device__ bf16 g_vh[(size_t)MROWS * DIMC];
__device__ bf16 g_vl[(size_t)MROWS * DIMC];
__device__ bf16 g_wqh[(size_t)DIMC * DIMC];
__device__ bf16 g_wql[(size_t)DIMC * DIMC];
__device__ bf16 g_wkh[(size_t)DIMC * DIMC];
__device__ bf16 g_wkl[(size_t)DIMC * DIMC];
__device__ bf16 g_wvh[(size_t)DIMC * DIMC];
__device__ bf16 g_wvl[(size_t)DIMC * DIMC];
__device__ bf16 g_woh[(size_t)DIMC * DIMC];
__device__ bf16 g_wol[(size_t)DIMC * DIMC];
__device__ bf16 g_pqh[(size_t)MROWS * DIMC];
__device__ bf16 g_pql[(size_t)MROWS * DIMC];
__device__ bf16 g_pkh[(size_t)MROWS * DIMC];
__device__ bf16 g_pkl[(size_t)MROWS * DIMC];
__device__ bf16 g_pvh[(size_t)MROWS * DIMC];
__device__ bf16 g_pvl[(size_t)MROWS * DIMC];
__device__ bf16 g_aoh[(size_t)MROWS * DIMC];
__device__ bf16 g_aol[(size_t)MROWS * DIMC];

// ---------------------------------------------------------------------------
// Helpers
// ---------------------------------------------------------------------------
__device__ __forceinline__ uint32_t smem_u32(const void* p) {
    uint32_t a;
    asm("{ .reg .u64 t; cvta.to.shared.u64 t, %1; cvt.u32.u64 %0, t; }" : "=r"(a) : "l"(p));
    return a;
}
__device__ __forceinline__ void cpa16(uint32_t dst, const void* src) {
    asm volatile("cp.async.cg.shared.global [%0], [%1], 16;" :: "r"(dst), "l"(src) : "memory");
}
#define CP_COMMIT() asm volatile("cp.async.commit_group;" ::: "memory")
#define CP_WAIT(n)  asm volatile("cp.async.wait_group %0;" :: "n"(n) : "memory")

__device__ __forceinline__ void ldsm_x4(uint32_t& r0, uint32_t& r1, uint32_t& r2, uint32_t& r3,
                                        uint32_t addr) {
    asm volatile("ldmatrix.sync.aligned.m8n8.x4.shared.b16 {%0,%1,%2,%3}, [%4];"
                 : "=r"(r0), "=r"(r1), "=r"(r2), "=r"(r3) : "r"(addr));
}
__device__ __forceinline__ void ldsm_x4_t(uint32_t& r0, uint32_t& r1, uint32_t& r2, uint32_t& r3,
                                          uint32_t addr) {
    asm volatile("ldmatrix.sync.aligned.m8n8.x4.trans.shared.b16 {%0,%1,%2,%3}, [%4];"
                 : "=r"(r0), "=r"(r1), "=r"(r2), "=r"(r3) : "r"(addr));
}
__device__ __forceinline__ void mma16816(float* c, uint32_t a0, uint32_t a1, uint32_t a2,
                                         uint32_t a3, uint32_t b0, uint32_t b1) {
    asm volatile(
        "mma.sync.aligned.m16n8k16.row.col.f32.bf16.bf16.f32 "
        "{%0,%1,%2,%3}, {%4,%5,%6,%7}, {%8,%9}, {%0,%1,%2,%3};"
        : "+f"(c[0]), "+f"(c[1]), "+f"(c[2]), "+f"(c[3])
        : "r"(a0), "r"(a1), "r"(a2), "r"(a3), "r"(b0), "r"(b1));
}
__device__ __forceinline__ uint32_t pack_hi(float a, float b) {
    __nv_bfloat162 h = __floats2bfloat162_rn(a, b);
    return *(uint32_t*)&h;
}
__device__ __forceinline__ uint32_t pack_lo(float a, float b) {
    float ra = a - __bfloat162float(__float2bfloat16(a));
    float rb = b - __bfloat162float(__float2bfloat16(b));
    __nv_bfloat162 h = __floats2bfloat162_rn(ra, rb);
    return *(uint32_t*)&h;
}

// ---------------------------------------------------------------------------
// fp32 -> bf16 hi/lo splits (fused: z selects operand)
// ---------------------------------------------------------------------------
__device__ __forceinline__ void split_one(const float* __restrict__ src,
                                          bf16* __restrict__ hi, bf16* __restrict__ lo,
                                          int n) {
    int i = (blockIdx.x * blockDim.x + threadIdx.x) * 4;
    if (i >= n) return;
    float4 v = *(const float4*)(src + i);
    *(uint32_t*)(hi + i) = pack_hi(v.x, v.y);
    *(uint32_t*)(hi + i + 2) = pack_hi(v.z, v.w);
    *(uint32_t*)(lo + i) = pack_lo(v.x, v.y);
    *(uint32_t*)(lo + i + 2) = pack_lo(v.z, v.w);
}

__global__ void split_acts(const float* __restrict__ q, const float* __restrict__ k,
                           const float* __restrict__ v,
                           bf16* qh, bf16* ql, bf16* kh, bf16* kl, bf16* vh, bf16* vl) {
    const int z = blockIdx.z;
    const float* s = (z == 0) ? q : (z == 1) ? k : v;
    bf16* h = (z == 0) ? qh : (z == 1) ? kh : vh;
    bf16* l = (z == 0) ? ql : (z == 1) ? kl : vl;
    split_one(s, h, l, MROWS * DIMC);
}

__global__ void split_wts(const float* __restrict__ wq, const float* __restrict__ wk,
                          const float* __restrict__ wv, const float* __restrict__ wo,
                          bf16* wqh, bf16* wql, bf16* wkh, bf16* wkl,
                          bf16* wvh, bf16* wvl, bf16* woh, bf16* wol) {
    const int z = blockIdx.z;
    const float* s = (z == 0) ? wq : (z == 1) ? wk : (z == 2) ? wv : wo;
    bf16* h = (z == 0) ? wqh : (z == 1) ? wkh : (z == 2) ? wvh : woh;
    bf16* l = (z == 0) ? wql : (z == 1) ? wkl : (z == 2) ? wvl : wol;
    split_one(s, h, l, DIMC * DIMC);
}

// ---------------------------------------------------------------------------
// HMMA bf16-split NT GEMM, 3-stage pipeline, BK=64.
// C = (Ah+Al)[M,K] @ (Bh+Bl)[N,K]^T + bias ; 3 passes Ah*Bh, Ah*Bl, Al*Bh.
// CTA 128x128, 8 warps (warp tile 32x64).
// ---------------------------------------------------------------------------
#define GPITCH 72                  /* bf16 elems per smem row (144 B, bank stride 4) */
#define GPITCHB (GPITCH * 2)
#define GSTAGE_ELEMS (128 * GPITCH)               /* per matrix per stage */
#define GSTAGE_BYTES (GSTAGE_ELEMS * 2)           /* 18432 */
#define GEMM_SMEM (3 * 2 * GSTAGE_BYTES)          /* 110592 */

__device__ __forceinline__ void ld_chunk64(
    uint32_t a_s, uint32_t b_s,
    const bf16* __restrict__ A, const bf16* __restrict__ B,
    int bm, int bn, int ks, int K, int tid)
{
#pragma unroll
    for (int it = 0; it < 4; it++) {
        int f = tid + it * 256;   // 0..1023
        int r = f >> 3;           // 0..127
        int c = f & 7;            // 16B unit within 128B of row data
        cpa16(a_s + r * GPITCHB + c * 16, A + (size_t)(bm + r) * K + ks + c * 8);
        cpa16(b_s + r * GPITCHB + c * 16, B + (size_t)(bn + r) * K + ks + c * 8);
    }
}

template <bool SPLIT>
__device__ __forceinline__ void gemm_mma_body(
    const bf16* __restrict__ Ah, const bf16* __restrict__ Al,
    const bf16* __restrict__ Bh, const bf16* __restrict__ Bl,
    const float* __restrict__ bias, float* __restrict__ Cf,
    bf16* __restrict__ Chi, bf16* __restrict__ Clo,
    int M, int N, int K)
{
    extern __shared__ char gsm[];
    const uint32_t sb = smem_u32(gsm);

    const int tid = threadIdx.x;
    const int wid = tid >> 5;
    const int lane = tid & 31;
    const int wm = wid & 3;
    const int wn = wid >> 2;
    const int bm = blockIdx.y * 128;
    const int bn = blockIdx.x * 128;

    float acc[2][8][4];
#pragma unroll
    for (int mt = 0; mt < 2; mt++)
#pragma unroll
        for (int j = 0; j < 8; j++)
#pragma unroll
            for (int q = 0; q < 4; q++) acc[mt][j][q] = 0.0f;

    const int kchunks = K >> 6;          // 16
    const int nch = 3 * kchunks;         // 48
    const bf16* Asrc[3] = { Ah, Ah, Al };
    const bf16* Bsrc[3] = { Bh, Bl, Bh };

    const int lrow = (lane & 7) + (((lane >> 3) & 1) << 3);
    const int lk8 = ((lane >> 4) & 1) << 3;

    auto a_st = [&](int s) { return sb + (uint32_t)s * 2 * GSTAGE_BYTES; };
    auto b_st = [&](int s) { return sb + (uint32_t)s * 2 * GSTAGE_BYTES + GSTAGE_BYTES; };

    // prologue: stages 0, 1
#pragma unroll
    for (int s = 0; s < 2; s++) {
        const int pass = s / kchunks;
        const int ks = (s % kchunks) << 6;
        ld_chunk64(a_st(s), b_st(s), Asrc[pass], Bsrc[pass], bm, bn, ks, K, tid);
        CP_COMMIT();
    }
    CP_WAIT(1);
    __syncthreads();

    uint32_t af[2][2][4];   // [buf][mt][frag]
    uint32_t bfr[2][8][2];  // [buf][j][frag]

    auto ld_frags = [&](uint32_t a_base, uint32_t b_base, int ks16, int buf) {
#pragma unroll
        for (int mt = 0; mt < 2; mt++) {
            uint32_t addr = a_base +
                (uint32_t)((wm * 32 + mt * 16 + lrow) * GPITCHB + (ks16 + lk8) * 2);
            ldsm_x4(af[buf][mt][0], af[buf][mt][1], af[buf][mt][2], af[buf][mt][3], addr);
        }
#pragma unroll
        for (int jp = 0; jp < 4; jp++) {
            uint32_t addr = b_base +
                (uint32_t)((wn * 64 + jp * 16 + lrow) * GPITCHB + (ks16 + lk8) * 2);
            uint32_t r0, r1, r2, r3;
            ldsm_x4(r0, r1, r2, r3, addr);
            bfr[buf][jp * 2 + 0][0] = r0; bfr[buf][jp * 2 + 0][1] = r2;
            bfr[buf][jp * 2 + 1][0] = r1; bfr[buf][jp * 2 + 1][1] = r3;
        }
    };

    for (int c = 0; c < nch; c++) {
        const int cs = c % 3;
        const uint32_t a_base = a_st(cs);
        const uint32_t b_base = b_st(cs);

        ld_frags(a_base, b_base, 0, 0);

        // issue loads for stage c+2 (slot consumed at iter c-1; WAR-safe past sync(c-1))
        const bool have_next = (c + 2 < nch);
        if (have_next) {
            const int cn = c + 2;
            const int pass = cn / kchunks;
            const int ks = (cn % kchunks) << 6;
            ld_chunk64(a_st((c + 2) % 3), b_st((c + 2) % 3),
                       Asrc[pass], Bsrc[pass], bm, bn, ks, K, tid);
            CP_COMMIT();
        }

#pragma unroll
        for (int k16 = 0; k16 < 4; k16++) {
            const int cur = k16 & 1;
            if (k16 < 3) ld_frags(a_base, b_base, (k16 + 1) * 16, cur ^ 1);
#pragma unroll
            for (int mt = 0; mt < 2; mt++)
#pragma unroll
                for (int j = 0; j < 8; j++)
                    mma16816(acc[mt][j],
                             af[cur][mt][0], af[cur][mt][1], af[cur][mt][2], af[cur][mt][3],
                             bfr[cur][j][0], bfr[cur][j][1]);
        }

        if (have_next) { CP_WAIT(1); } else { CP_WAIT(0); }
        __syncthreads();
    }

    const int g = lane >> 2;
    const int t = lane & 3;
#pragma unroll
    for (int mt = 0; mt < 2; mt++) {
        const int row0 = bm + wm * 32 + mt * 16 + g;
#pragma unroll
        for (int j = 0; j < 8; j++) {
            const int col = bn + wn * 64 + j * 8 + t * 2;
            const float b0 = bias[col], b1 = bias[col + 1];
            float f0 = acc[mt][j][0] + b0, f1 = acc[mt][j][1] + b1;
            float f2 = acc[mt][j][2] + b0, f3 = acc[mt][j][3] + b1;
            if (SPLIT) {
                *(uint32_t*)(Chi + (size_t)row0 * N + col) = pack_hi(f0, f1);
                *(uint32_t*)(Clo + (size_t)row0 * N + col) = pack_lo(f0, f1);
                *(uint32_t*)(Chi + (size_t)(row0 + 8) * N + col) = pack_hi(f2, f3);
                *(uint32_t*)(Clo + (size_t)(row0 + 8) * N + col) = pack_lo(f2, f3);
            } else {
                *(float2*)(Cf + (size_t)row0 * N + col) = make_float2(f0, f1);
                *(float2*)(Cf + (size_t)(row0 + 8) * N + col) = make_float2(f2, f3);
            }
        }
    }
}

__global__ __launch_bounds__(256) void gemm_mma_out(
    const bf16* __restrict__ Ah, const bf16* __restrict__ Al,
    const bf16* __restrict__ Bh, const bf16* __restrict__ Bl,
    const float* __restrict__ bias, float* __restrict__ C, int M, int N, int K)
{
    gemm_mma_body<false>(Ah, Al, Bh, Bl, bias, C, nullptr, nullptr, M, N, K);
}

__global__ __launch_bounds__(256) void gemm_mma_qkv(
    const bf16* __restrict__ qh, const bf16* __restrict__ ql,
    const bf16* __restrict__ kh, const bf16* __restrict__ kl,
    const bf16* __restrict__ vh, const bf16* __restrict__ vl,
    const bf16* __restrict__ wqh, const bf16* __restrict__ wql,
    const bf16* __restrict__ wkh, const bf16* __restrict__ wkl,
    const bf16* __restrict__ wvh, const bf16* __restrict__ wvl,
    const float* __restrict__ bq, const float* __restrict__ bk, const float* __restrict__ bv,
    bf16* __restrict__ pqh, bf16* __restrict__ pql,
    bf16* __restrict__ pkh, bf16* __restrict__ pkl,
    bf16* __restrict__ pvh, bf16* __restrict__ pvl)
{
    const int z = blockIdx.z;
    const bf16* Ah = (z == 0) ? qh : (z == 1) ? kh : vh;
    const bf16* Al = (z == 0) ? ql : (z == 1) ? kl : vl;
    const bf16* Bh = (z == 0) ? wqh : (z == 1) ? wkh : wvh;
    const bf16* Bl = (z == 0) ? wql : (z == 1) ? wkl : wvl;
    const float* bias = (z == 0) ? bq : (z == 1) ? bk : bv;
    bf16* Chi = (z == 0) ? pqh : (z == 1) ? pkh : pvh;
    bf16* Clo = (z == 0) ? pql : (z == 1) ? pkl : pvl;
    gemm_mma_body<true>(Ah, Al, Bh, Bl, bias, nullptr, Chi, Clo, MROWS, DIMC, DIMC);
}

// ---------------------------------------------------------------------------
// HMMA flash attention (unchanged from R4).
// ---------------------------------------------------------------------------
#define KVP 72
#define KV_STAGE_ELEMS (4 * 64 * KVP)
#define ATTN_SMEM (2 * KV_STAGE_ELEMS * 2)

__global__ __launch_bounds__(256) void attn_mma(
    const bf16* __restrict__ Qh, const bf16* __restrict__ Ql,
    const bf16* __restrict__ Kh, const bf16* __restrict__ Kl,
    const bf16* __restrict__ Vh, const bf16* __restrict__ Vl,
    const int* __restrict__ mask, bf16* __restrict__ Oh, bf16* __restrict__ Ol)
{
    extern __shared__ bf16 kv[];
    const uint32_t kvb = smem_u32(kv);
    const int tid = threadIdx.x;
    const int wid = tid >> 5;
    const int lane = tid & 31;
    const int t = lane & 3;
    const int g = lane >> 2;
    const int q0 = blockIdx.x * 128;
    const int h = blockIdx.y;
    const int b = blockIdx.z;

    const size_t rowg = (size_t)b * TQ + q0 + wid * 16 + g;
    const size_t rowg8 = rowg + 8;
    uint32_t aqh[4][4], aql[4][4];
#pragma unroll
    for (int c = 0; c < 4; c++) {
        const int col = h * HEAD_DIM + c * 16 + t * 2;
        aqh[c][0] = *(const uint32_t*)(Qh + rowg * DIMC + col);
        aqh[c][1] = *(const uint32_t*)(Qh + rowg8 * DIMC + col);
        aqh[c][2] = *(const uint32_t*)(Qh + rowg * DIMC + col + 8);
        aqh[c][3] = *(const uint32_t*)(Qh + rowg8 * DIMC + col + 8);
        aql[c][0] = *(const uint32_t*)(Ql + rowg * DIMC + col);
        aql[c][1] = *(const uint32_t*)(Ql + rowg8 * DIMC + col);
        aql[c][2] = *(const uint32_t*)(Ql + rowg * DIMC + col + 8);
        aql[c][3] = *(const uint32_t*)(Ql + rowg8 * DIMC + col + 8);
    }

    float m_[2] = { -1e30f, -1e30f };
    float l_[2] = { 0.0f, 0.0f };
    float acc_o[8][4];
#pragma unroll
    for (int j = 0; j < 8; j++)
#pragma unroll
        for (int q = 0; q < 4; q++) acc_o[j][q] = 0.0f;

    auto ld_kv = [&](int kt, int s) {
        const size_t rbase = (size_t)b * TK + kt * 64;
#pragma unroll
        for (int i = 0; i < 8; i++) {
            int f = tid + i * 256;
            int arr = f >> 9;
            int idx = f & 511;
            int r = idx >> 3, c8 = idx & 7;
            const bf16* src = (arr == 0) ? Kh : (arr == 1) ? Kl : (arr == 2) ? Vh : Vl;
            uint32_t dst = kvb + (uint32_t)(s * KV_STAGE_ELEMS + arr * (64 * KVP) +
                                            r * KVP + c8 * 8) * 2;
            cpa16(dst, src + (rbase + r) * DIMC + h * HEAD_DIM + c8 * 8);
        }
    };

    ld_kv(0, 0);
    CP_COMMIT();

    const int lrow = (lane & 7) + (((lane >> 3) & 1) << 3);
    const int lk8 = ((lane >> 4) & 1) << 3;
    const int trow = (lane & 7) + (((lane >> 3) & 1) << 3);
    const int tcol = ((lane >> 4) & 1) << 3;

    const size_t mrow0 = ((size_t)b * TQ + q0 + wid * 16 + g) * TK;
    const size_t mrow1 = mrow0 + 8 * TK;

    for (int kt = 0; kt < TK / 64; kt++) {
        const int cb = kt & 1;
        const int nb = cb ^ 1;
        if (kt + 1 < TK / 64) {
            ld_kv(kt + 1, nb);
            CP_COMMIT();
            CP_WAIT(1);
        } else {
            CP_WAIT(0);
        }
        __syncthreads();

        const uint32_t KHb = kvb + (uint32_t)(cb * KV_STAGE_ELEMS) * 2;
        const uint32_t KLb = KHb + (64 * KVP) * 2;
        const uint32_t VHb = KHb + (2 * 64 * KVP) * 2;
        const uint32_t VLb = KHb + (3 * 64 * KVP) * 2;

        float acc_s[8][4];
#pragma unroll
        for (int j = 0; j < 8; j++)
#pragma unroll
            for (int q = 0; q < 4; q++) acc_s[j][q] = 0.0f;

#pragma unroll
        for (int pass = 0; pass < 3; pass++) {
            const uint32_t(*aq)[4] = (pass == 2) ? aql : aqh;
            const uint32_t Kb = (pass == 1) ? KLb : KHb;
#pragma unroll
            for (int c = 0; c < 4; c++) {
                uint32_t bfr[8][2];
#pragma unroll
                for (int jp = 0; jp < 4; jp++) {
                    uint32_t addr = Kb + (uint32_t)((jp * 16 + lrow) * KVP + c * 16 + lk8) * 2;
                    uint32_t r0, r1, r2, r3;
                    ldsm_x4(r0, r1, r2, r3, addr);
                    bfr[jp * 2 + 0][0] = r0; bfr[jp * 2 + 0][1] = r2;
                    bfr[jp * 2 + 1][0] = r1; bfr[jp * 2 + 1][1] = r3;
                }
#pragma unroll
                for (int j = 0; j < 8; j++)
                    mma16816(acc_s[j], aq[c][0], aq[c][1], aq[c][2], aq[c][3],
                             bfr[j][0], bfr[j][1]);
            }
        }

        const int kc0 = kt * 64;
#pragma unroll
        for (int r01 = 0; r01 < 2; r01++) {
            const size_t mrow = ((r01 == 0) ? mrow0 : mrow1) + kc0;
            float mx = -1e30f;
#pragma unroll
            for (int j = 0; j < 8; j++) {
                int2 mm = *(const int2*)(mask + mrow + j * 8 + t * 2);
                float s0 = fminf(fmaxf(acc_s[j][r01 * 2 + 0] * 0.125f, -100.0f), 100.0f);
                float s1 = fminf(fmaxf(acc_s[j][r01 * 2 + 1] * 0.125f, -100.0f), 100.0f);
                s0 = (mm.x == 0) ? -1e30f : s0;
                s1 = (mm.y == 0) ? -1e30f : s1;
                acc_s[j][r01 * 2 + 0] = s0;
                acc_s[j][r01 * 2 + 1] = s1;
                mx = fmaxf(mx, fmaxf(s0, s1));
            }
            mx = fmaxf(mx, __shfl_xor_sync(0xffffffffu, mx, 1));
            mx = fmaxf(mx, __shfl_xor_sync(0xffffffffu, mx, 2));
            const float mnew = fmaxf(m_[r01], mx);
            const float alpha = __expf(m_[r01] - mnew);
            float rs = 0.0f;
#pragma unroll
            for (int j = 0; j < 8; j++) {
                float p0 = __expf(acc_s[j][r01 * 2 + 0] - mnew);
                float p1 = __expf(acc_s[j][r01 * 2 + 1] - mnew);
                acc_s[j][r01 * 2 + 0] = p0;
                acc_s[j][r01 * 2 + 1] = p1;
                rs += p0 + p1;
            }
            rs += __shfl_xor_sync(0xffffffffu, rs, 1);
            rs += __shfl_xor_sync(0xffffffffu, rs, 2);
            l_[r01] = l_[r01] * alpha + rs;
            m_[r01] = mnew;
#pragma unroll
            for (int j = 0; j < 8; j++) {
                acc_o[j][r01 * 2 + 0] *= alpha;
                acc_o[j][r01 * 2 + 1] *= alpha;
            }
        }

#pragma unroll
        for (int c = 0; c < 4; c++) {
            uint32_t ph[4], pl[4];
            ph[0] = pack_hi(acc_s[2 * c][0], acc_s[2 * c][1]);
            ph[1] = pack_hi(acc_s[2 * c][2], acc_s[2 * c][3]);
            ph[2] = pack_hi(acc_s[2 * c + 1][0], acc_s[2 * c + 1][1]);
            ph[3] = pack_hi(acc_s[2 * c + 1][2], acc_s[2 * c + 1][3]);
            pl[0] = pack_lo(acc_s[2 * c][0], acc_s[2 * c][1]);
            pl[1] = pack_lo(acc_s[2 * c][2], acc_s[2 * c][3]);
            pl[2] = pack_lo(acc_s[2 * c + 1][0], acc_s[2 * c + 1][1]);
            pl[3] = pack_lo(acc_s[2 * c + 1][2], acc_s[2 * c + 1][3]);
#pragma unroll
            for (int u = 0; u < 4; u++) {
                const uint32_t off = (uint32_t)((c * 16 + trow) * KVP + u * 16 + tcol) * 2;
                uint32_t vh0, vh1, vh2, vh3, vl0, vl1, vl2, vl3;
                ldsm_x4_t(vh0, vh1, vh2, vh3, VHb + off);
                ldsm_x4_t(vl0, vl1, vl2, vl3, VLb + off);
                mma16816(acc_o[2 * u + 0], ph[0], ph[1], ph[2], ph[3], vh0, vh1);
                mma16816(acc_o[2 * u + 1], ph[0], ph[1], ph[2], ph[3], vh2, vh3);
                mma16816(acc_o[2 * u + 0], ph[0], ph[1], ph[2], ph[3], vl0, vl1);
                mma16816(acc_o[2 * u + 1], ph[0], ph[1], ph[2], ph[3], vl2, vl3);
                mma16816(acc_o[2 * u + 0], pl[0], pl[1], pl[2], pl[3], vh0, vh1);
                mma16816(acc_o[2 * u + 1], pl[0], pl[1], pl[2], pl[3], vh2, vh3);
            }
        }
        __syncthreads();
    }

    const float inv0 = 1.0f / l_[0];
    const float inv1 = 1.0f / l_[1];
#pragma unroll
    for (int j = 0; j < 8; j++) {
        const int col = h * HEAD_DIM + j * 8 + t * 2;
        float f0 = acc_o[j][0] * inv0, f1 = acc_o[j][1] * inv0;
        float f2 = acc_o[j][2] * inv1, f3 = acc_o[j][3] * inv1;
        *(uint32_t*)(Oh + rowg * DIMC + col) = pack_hi(f0, f1);
        *(uint32_t*)(Ol + rowg * DIMC + col) = pack_lo(f0, f1);
        *(uint32_t*)(Oh + rowg8 * DIMC + col) = pack_hi(f2, f3);
        *(uint32_t*)(Ol + rowg8 * DIMC + col) = pack_lo(f2, f3);
    }
}

// ---------------------------------------------------------------------------
extern "C" void kernel_launch(void* const* d_in, const int* in_sizes, int n_in,
                              void* d_out, int out_size)
{
    const float* query = (const float*)d_in[0];
    const float* key = (const float*)d_in[1];
    const float* value = (const float*)d_in[2];
    const int* mask = (const int*)d_in[3];
    const float* wq = (const float*)d_in[4];
    const float* wk = (const float*)d_in[5];
    const float* wv = (const float*)d_in[6];
    const float* wo = (const float*)d_in[7];
    const float* bq = (const float*)d_in[8];
    const float* bk = (const float*)d_in[9];
    const float* bv = (const float*)d_in[10];
    const float* bo = (const float*)d_in[11];

    bf16 *qh, *ql, *kh, *kl, *vh, *vl;
    bf16 *wqh, *wql, *wkh, *wkl, *wvh, *wvl, *woh, *wol;
    bf16 *pqh, *pql, *pkh, *pkl, *pvh, *pvl, *aoh, *aol;
    cudaGetSymbolAddress((void**)&qh, g_qh);   cudaGetSymbolAddress((void**)&ql, g_ql);
    cudaGetSymbolAddress((void**)&kh, g_kh);   cudaGetSymbolAddress((void**)&kl, g_kl);
    cudaGetSymbolAddress((void**)&vh, g_vh);   cudaGetSymbolAddress((void**)&vl, g_vl);
    cudaGetSymbolAddress((void**)&wqh, g_wqh); cudaGetSymbolAddress((void**)&wql, g_wql);
    cudaGetSymbolAddress((void**)&wkh, g_wkh); cudaGetSymbolAddress((void**)&wkl, g_wkl);
    cudaGetSymbolAddress((void**)&wvh, g_wvh); cudaGetSymbolAddress((void**)&wvl, g_wvl);
    cudaGetSymbolAddress((void**)&woh, g_woh); cudaGetSymbolAddress((void**)&wol, g_wol);
    cudaGetSymbolAddress((void**)&pqh, g_pqh); cudaGetSymbolAddress((void**)&pql, g_pql);
    cudaGetSymbolAddress((void**)&pkh, g_pkh); cudaGetSymbolAddress((void**)&pkl, g_pkl);
    cudaGetSymbolAddress((void**)&pvh, g_pvh); cudaGetSymbolAddress((void**)&pvl, g_pvl);
    cudaGetSymbolAddress((void**)&aoh, g_aoh); cudaGetSymbolAddress((void**)&aol, g_aol);

    static int attr_set = 0;
    if (!attr_set) {
        cudaFuncSetAttribute(attn_mma, cudaFuncAttributeMaxDynamicSharedMemorySize, ATTN_SMEM);
        cudaFuncSetAttribute(gemm_mma_qkv, cudaFuncAttributeMaxDynamicSharedMemorySize, GEMM_SMEM);
        cudaFuncSetAttribute(gemm_mma_out, cudaFuncAttributeMaxDynamicSharedMemorySize, GEMM_SMEM);
        attr_set = 1;
    }

    const int nAct = MROWS * DIMC;
    const int nW = DIMC * DIMC;

    dim3 gsa(nAct / 1024, 1, 3);
    split_acts<<<gsa, 256>>>(query, key, value, qh, ql, kh, kl, vh, vl);
    dim3 gsw(nW / 1024, 1, 4);
    split_wts<<<gsw, 256>>>(wq, wk, wv, wo, wqh, wql, wkh, wkl, wvh, wvl, woh, wol);

    dim3 gqkv(DIMC / 128, MROWS / 128, 3);
    gemm_mma_qkv<<<gqkv, 256, GEMM_SMEM>>>(qh, ql, kh, kl, vh, vl,
                                           wqh, wql, wkh, wkl, wvh, wvl,
                                           bq, bk, bv,
                                           pqh, pql, pkh, pkl, pvh, pvl);

    dim3 gattn(TQ / 128, HEADS, BATCH);
    attn_mma<<<gattn, 256, ATTN_SMEM>>>(pqh, pql, pkh, pkl, pvh, pvl, mask, aoh, aol);

    dim3 gout(DIMC / 128, MROWS / 128);
    gemm_mma_out<<<gout, 256, GEMM_SMEM>>>(aoh, aol, woh, wol, bo, (float*)d_out,
                                           MROWS, DIMC, DIMC);
}